// round 2
// baseline (speedup 1.0000x reference)
#include <cuda_runtime.h>
#include <math.h>

#define Bb 2
#define Ss 2048
#define Hh 1024
#define NHh 16
#define Dd 64
#define MROWS (Bb * Ss)   // 4096

// Scratch (no cudaMalloc allowed): Q, K, V, ctx each [4096, 1024] fp32 = 16 MiB
__device__ float g_q[MROWS * Hh];
__device__ float g_k[MROWS * Hh];
__device__ float g_v[MROWS * Hh];
__device__ float g_ctx[MROWS * Hh];

// ---------------------------------------------------------------------------
// GEMM (NT): C[m][n] = sum_k A[m][k] * B[n][k] + bias[n]
// M=4096, N=1024, K=1024. Block tile 128x128, K-tile 16, 256 threads, 8x8/thr.
// ---------------------------------------------------------------------------
__global__ void __launch_bounds__(256) gemm_nt_bias(
    const float* __restrict__ A, const float* __restrict__ B,
    const float* __restrict__ bias, float* __restrict__ C)
{
    const int K = 1024, N = 1024;
    __shared__ float As[16][132];
    __shared__ float Bs[16][132];

    const int tid = threadIdx.x;
    const int tx = tid % 16;          // n direction
    const int ty = tid / 16;          // m direction
    const int m0 = blockIdx.y * 128;
    const int n0 = blockIdx.x * 128;

    const int lr = tid / 4;           // 0..63
    const int lc = (tid % 4) * 4;     // 0,4,8,12

    float acc[8][8];
#pragma unroll
    for (int i = 0; i < 8; i++)
#pragma unroll
        for (int j = 0; j < 8; j++) acc[i][j] = 0.f;

    for (int k0 = 0; k0 < K; k0 += 16) {
#pragma unroll
        for (int h = 0; h < 2; h++) {
            int r = lr + h * 64;
            float4 a = *(const float4*)&A[(size_t)(m0 + r) * K + k0 + lc];
            As[lc + 0][r] = a.x; As[lc + 1][r] = a.y;
            As[lc + 2][r] = a.z; As[lc + 3][r] = a.w;
            float4 b = *(const float4*)&B[(size_t)(n0 + r) * K + k0 + lc];
            Bs[lc + 0][r] = b.x; Bs[lc + 1][r] = b.y;
            Bs[lc + 2][r] = b.z; Bs[lc + 3][r] = b.w;
        }
        __syncthreads();

#pragma unroll
        for (int kk = 0; kk < 16; kk++) {
            float4 a0 = *(const float4*)&As[kk][ty * 8];
            float4 a1 = *(const float4*)&As[kk][ty * 8 + 4];
            float4 b0 = *(const float4*)&Bs[kk][tx * 8];
            float4 b1 = *(const float4*)&Bs[kk][tx * 8 + 4];
            float ra[8] = {a0.x, a0.y, a0.z, a0.w, a1.x, a1.y, a1.z, a1.w};
            float rb[8] = {b0.x, b0.y, b0.z, b0.w, b1.x, b1.y, b1.z, b1.w};
#pragma unroll
            for (int i = 0; i < 8; i++)
#pragma unroll
                for (int j = 0; j < 8; j++)
                    acc[i][j] = fmaf(ra[i], rb[j], acc[i][j]);
        }
        __syncthreads();
    }

#pragma unroll
    for (int i = 0; i < 8; i++) {
        int row = m0 + ty * 8 + i;
#pragma unroll
        for (int j = 0; j < 8; j += 4) {
            int col = n0 + tx * 8 + j;
            float4 bb = *(const float4*)&bias[col];
            float4 c;
            c.x = acc[i][j + 0] + bb.x;
            c.y = acc[i][j + 1] + bb.y;
            c.z = acc[i][j + 2] + bb.z;
            c.w = acc[i][j + 3] + bb.w;
            *(float4*)&C[(size_t)row * N + col] = c;
        }
    }
}

// ---------------------------------------------------------------------------
// Flash attention: per (b,h) head, query tile Br=64, key tile Bc=32,
// online softmax, fp32. 256 threads: row r = tid/4, column-group cg = tid%4.
// Q/K/V live in g_q/g_k/g_v as [B*S, H] with head columns h*64..h*64+63.
// Output -> g_ctx in concat layout [B*S, H].
// ---------------------------------------------------------------------------
__global__ void __launch_bounds__(256) attn_kernel()
{
    const int bh = blockIdx.y;           // 0..31
    const int b  = bh / NHh;
    const int h  = bh % NHh;
    const int q0 = blockIdx.x * 64;

    __shared__ float sQ[64][68];
    __shared__ float sK[32][68];
    __shared__ float sV[32][68];
    __shared__ float sP[64][36];

    const int tid = threadIdx.x;
    const float* Qb = g_q + (size_t)(b * Ss) * Hh + h * Dd;
    const float* Kb = g_k + (size_t)(b * Ss) * Hh + h * Dd;
    const float* Vb = g_v + (size_t)(b * Ss) * Hh + h * Dd;

    // Load Q tile: 64 rows x 64 cols = 1024 float4
    for (int i = tid; i < 64 * 16; i += 256) {
        int r = i / 16, c4 = (i % 16) * 4;
        *(float4*)&sQ[r][c4] = *(const float4*)&Qb[(size_t)(q0 + r) * Hh + c4];
    }

    const int r  = tid / 4;   // row within tile
    const int cg = tid % 4;   // column group

    float m = -1e30f, l = 0.f;
    float o[16];
#pragma unroll
    for (int j = 0; j < 16; j++) o[j] = 0.f;

    for (int kt = 0; kt < Ss; kt += 32) {
        __syncthreads();   // previous PV done reading sK/sV
        for (int i = tid; i < 32 * 16; i += 256) {
            int rr = i / 16, c4 = (i % 16) * 4;
            *(float4*)&sK[rr][c4] = *(const float4*)&Kb[(size_t)(kt + rr) * Hh + c4];
            *(float4*)&sV[rr][c4] = *(const float4*)&Vb[(size_t)(kt + rr) * Hh + c4];
        }
        __syncthreads();

        // S tile: this thread computes cols cg*8 .. cg*8+7 for row r
        float s[8];
#pragma unroll
        for (int c = 0; c < 8; c++) s[c] = 0.f;
#pragma unroll
        for (int d4 = 0; d4 < 64; d4 += 4) {
            float4 qv = *(const float4*)&sQ[r][d4];
#pragma unroll
            for (int c = 0; c < 8; c++) {
                float4 kv = *(const float4*)&sK[cg * 8 + c][d4];
                s[c] = fmaf(qv.x, kv.x, s[c]);
                s[c] = fmaf(qv.y, kv.y, s[c]);
                s[c] = fmaf(qv.z, kv.z, s[c]);
                s[c] = fmaf(qv.w, kv.w, s[c]);
            }
        }

        float mt = -1e30f;
#pragma unroll
        for (int c = 0; c < 8; c++) {
            s[c] *= 0.125f;                    // 1/sqrt(64)
            mt = fmaxf(mt, s[c]);
        }
        mt = fmaxf(mt, __shfl_xor_sync(0xffffffffu, mt, 1));
        mt = fmaxf(mt, __shfl_xor_sync(0xffffffffu, mt, 2));

        float mnew  = fmaxf(m, mt);
        float alpha = __expf(m - mnew);
        float ls = 0.f;
#pragma unroll
        for (int c = 0; c < 8; c++) {
            float p = __expf(s[c] - mnew);
            ls += p;
            sP[r][cg * 8 + c] = p;
        }
        ls += __shfl_xor_sync(0xffffffffu, ls, 1);
        ls += __shfl_xor_sync(0xffffffffu, ls, 2);
        l = l * alpha + ls;
        m = mnew;
#pragma unroll
        for (int j = 0; j < 16; j++) o[j] *= alpha;

        __syncthreads();   // sP fully written

        // PV: this thread accumulates d-cols cg*16 .. +15 of row r
#pragma unroll
        for (int k = 0; k < 32; k++) {
            float p = sP[r][k];
            float4 v0 = *(const float4*)&sV[k][cg * 16 + 0];
            float4 v1 = *(const float4*)&sV[k][cg * 16 + 4];
            float4 v2 = *(const float4*)&sV[k][cg * 16 + 8];
            float4 v3 = *(const float4*)&sV[k][cg * 16 + 12];
            o[0]  = fmaf(p, v0.x, o[0]);  o[1]  = fmaf(p, v0.y, o[1]);
            o[2]  = fmaf(p, v0.z, o[2]);  o[3]  = fmaf(p, v0.w, o[3]);
            o[4]  = fmaf(p, v1.x, o[4]);  o[5]  = fmaf(p, v1.y, o[5]);
            o[6]  = fmaf(p, v1.z, o[6]);  o[7]  = fmaf(p, v1.w, o[7]);
            o[8]  = fmaf(p, v2.x, o[8]);  o[9]  = fmaf(p, v2.y, o[9]);
            o[10] = fmaf(p, v2.z, o[10]); o[11] = fmaf(p, v2.w, o[11]);
            o[12] = fmaf(p, v3.x, o[12]); o[13] = fmaf(p, v3.y, o[13]);
            o[14] = fmaf(p, v3.z, o[14]); o[15] = fmaf(p, v3.w, o[15]);
        }
    }

    const float inv = 1.f / l;
    float* outp = g_ctx + (size_t)(b * Ss + q0 + r) * Hh + h * Dd + cg * 16;
#pragma unroll
    for (int j = 0; j < 16; j += 4) {
        float4 c;
        c.x = o[j + 0] * inv; c.y = o[j + 1] * inv;
        c.z = o[j + 2] * inv; c.w = o[j + 3] * inv;
        *(float4*)&outp[j] = c;
    }
}

// ---------------------------------------------------------------------------
extern "C" void kernel_launch(void* const* d_in, const int* in_sizes, int n_in,
                              void* d_out, int out_size)
{
    const float* x  = (const float*)d_in[0];
    const float* wq = (const float*)d_in[1];
    const float* bq = (const float*)d_in[2];
    const float* wk = (const float*)d_in[3];
    const float* bk = (const float*)d_in[4];
    const float* wv = (const float*)d_in[5];
    const float* bv = (const float*)d_in[6];
    const float* wo = (const float*)d_in[7];
    const float* bo = (const float*)d_in[8];
    float* out = (float*)d_out;

    float *q, *k, *v, *ctx;
    cudaGetSymbolAddress((void**)&q,   g_q);
    cudaGetSymbolAddress((void**)&k,   g_k);
    cudaGetSymbolAddress((void**)&v,   g_v);
    cudaGetSymbolAddress((void**)&ctx, g_ctx);

    dim3 gg(1024 / 128, MROWS / 128);   // (8, 32)
    gemm_nt_bias<<<gg, 256>>>(x, wq, bq, q);
    gemm_nt_bias<<<gg, 256>>>(x, wk, bk, k);
    gemm_nt_bias<<<gg, 256>>>(x, wv, bv, v);

    dim3 ga(Ss / 64, Bb * NHh);         // (32, 32)
    attn_kernel<<<ga, 256>>>();

    gemm_nt_bias<<<gg, 256>>>(ctx, wo, bo, out);
}